// round 13
// baseline (speedup 1.0000x reference)
#include <cuda_runtime.h>

// ---------------------------------------------------------------------------
// DILATE loss. B=128, T=256, D=64, gamma=0.01, alpha=0.5, eps=1e-8, BIG=1e10.
//
// DIAGNOSTIC ROUND: fwd_kernel is launched TWICE (idempotent: pure function
// of g_D -> g_W, g_shape). dur_us - 255.5 measures fwd's duration exactly;
// this decides whether the remaining time is fwd's softmin chain or a
// universal per-phase floor. All kernel code is identical to the 255.5us best.
//
// Key identity retained from R12: forward softmin weights ARE the backward
// gradient edge weights; bwd is a pure linear recurrence on E*w products.
// ---------------------------------------------------------------------------

#define BATCH 128
#define TLEN  256
#define NDIAG 511            // 2*TLEN - 1
#define PAD   16             // diag padding each side (ring overshoot)
#define NDIAGT (NDIAG + 2 * PAD)
#define BIGV  1e10f
// exp(x/gamma) = exp2(x * KE2);  KE2 = (1/gamma)*log2(e)
#define KE2   144.26950408889634f
// gamma * ln(2)
#define KL    0.006931471805599453f

__device__ float  g_D[(size_t)BATCH * NDIAGT * TLEN];
__device__ float2 g_W[(size_t)BATCH * NDIAGT * TLEN];   // (w_diag, w_up) per cell
__device__ float  g_shape[BATCH];
__device__ float  g_num[BATCH];
__device__ float  g_den[BATCH];

__device__ __forceinline__ size_t DI(int b, int d, int i) {
    return ((size_t)b * NDIAGT + (d + PAD)) * TLEN + i;
}

__device__ __forceinline__ float ex2f_(float x) {
    float y; asm("ex2.approx.ftz.f32 %0, %1;" : "=f"(y) : "f"(x)); return y;
}
__device__ __forceinline__ float lg2f_(float x) {
    float y; asm("lg2.approx.ftz.f32 %0, %1;" : "=f"(y) : "f"(x)); return y;
}
__device__ __forceinline__ float rcpf_(float x) {
    float y; asm("rcp.approx.ftz.f32 %0, %1;" : "=f"(y) : "f"(x)); return y;
}

// ---------------------------------------------------------------------------
// Kernel 1: pairwise squared distances in diagonal layout (float4 smem).
// ---------------------------------------------------------------------------
__global__ __launch_bounds__(256) void dist_kernel(
    const float* __restrict__ preds, const float* __restrict__ targets)
{
    __shared__ float pool[2 * 64 * 68 + 128];
    float*  ps  = pool;                   // [64][68]
    float*  ts  = pool + 64 * 68;
    float*  pn  = pool + 2 * 64 * 68;     // [64]
    float*  tn  = pn + 64;
    float4* ps4 = (float4*)ps;            // pitch 17
    float4* ts4 = (float4*)ts;

    const int b  = blockIdx.z;
    const int i0 = blockIdx.y * 64;
    const int j0 = blockIdx.x * 64;
    const int tid = threadIdx.x;

    const float4* pb4 = (const float4*)(preds   + (size_t)b * TLEN * 64 + (size_t)i0 * 64);
    const float4* tb4 = (const float4*)(targets + (size_t)b * TLEN * 64 + (size_t)j0 * 64);

#pragma unroll
    for (int q = 0; q < 4; q++) {
        int idx = q * 256 + tid;          // 0..1023 float4s
        int r = idx >> 4, c4 = idx & 15;
        ps4[r * 17 + c4] = pb4[idx];
        ts4[r * 17 + c4] = tb4[idx];
    }
    __syncthreads();

    if (tid < 128) {
        const float* src = (tid < 64) ? ps : ts;
        float* dst = (tid < 64) ? pn : tn;
        int r = tid & 63;
        float s = 0.0f;
#pragma unroll
        for (int k = 0; k < 64; k++) { float v = src[r * 68 + k]; s = fmaf(v, v, s); }
        dst[r] = s;
    }
    __syncthreads();

    const int tx = tid & 15, ty = tid >> 4;
    const int ib = ty * 4, jb = tx * 4;

    float acc[4][4];
#pragma unroll
    for (int r = 0; r < 4; r++)
#pragma unroll
        for (int c = 0; c < 4; c++) acc[r][c] = 0.0f;

#pragma unroll 4
    for (int kq = 0; kq < 16; kq++) {
        float4 pv[4], tv[4];
#pragma unroll
        for (int r = 0; r < 4; r++) pv[r] = ps4[(ib + r) * 17 + kq];
#pragma unroll
        for (int c = 0; c < 4; c++) tv[c] = ts4[(jb + c) * 17 + kq];
#pragma unroll
        for (int r = 0; r < 4; r++)
#pragma unroll
            for (int c = 0; c < 4; c++) {
                acc[r][c] = fmaf(pv[r].x, tv[c].x, acc[r][c]);
                acc[r][c] = fmaf(pv[r].y, tv[c].y, acc[r][c]);
                acc[r][c] = fmaf(pv[r].z, tv[c].z, acc[r][c]);
                acc[r][c] = fmaf(pv[r].w, tv[c].w, acc[r][c]);
            }
    }

    float pnr[4], tnr[4];
#pragma unroll
    for (int r = 0; r < 4; r++) pnr[r] = pn[ib + r];
#pragma unroll
    for (int c = 0; c < 4; c++) tnr[c] = tn[jb + c];

    __syncthreads();

    // Stage tile diagonally: buf[tdd][ii], tdd = local i+j (0..126), pitch 65.
    float* buf = pool;
#pragma unroll
    for (int r = 0; r < 4; r++)
#pragma unroll
        for (int c = 0; c < 4; c++) {
            int ii = ib + r, jj = jb + c;
            float dv = pnr[r] + tnr[c] - 2.0f * acc[r][c];
            buf[(ii + jj) * 65 + ii] = fmaxf(dv, 0.0f);
        }
    __syncthreads();

    for (int base = 0; base < 128; base += 4) {
        int tdd = base + (tid >> 6);
        int ii  = tid & 63;
        if (tdd < 127) {
            int jj = tdd - ii;
            if (jj >= 0 && jj < 64)
                g_D[DI(b, i0 + j0 + tdd, i0 + ii)] = buf[tdd * 65 + ii];
        }
    }
}

// ---------------------------------------------------------------------------
// Kernel 2: soft-DTW forward. Phase p computes diags d=2p (Y), d+1 (Z) with
// halo X = R[d][i-1]. Ping-pong float2 smem sP[p&1][i+2] = (R_d[i], R_{d+1}[i]).
// Emits per-cell weights W=(w_dg,w_up) to g_W (deferred 1 phase). No g_R.
// ---------------------------------------------------------------------------
__global__ __launch_bounds__(256) void fwd_kernel()
{
    __shared__ float2 sP[2][260];   // [0..1] = BIG pad (never overwritten)
    const int b = blockIdx.x;
    const int i = threadIdx.x;

    for (int q = i; q < 2 * 260 * 2; q += 256) ((float*)sP)[q] = BIGV;
    __syncthreads();

    const float* Dbase  = g_D + ((size_t)b * NDIAGT + PAD) * TLEN;
    const float* Dp     = Dbase + i;
    const float* DpH    = Dbase + i - 1;   // halo column (pad rows keep i=0 safe)
    float2*      Wp     = g_W + ((size_t)b * NDIAGT + PAD) * TLEN + i;

    float rA[4], rB[4], rH[4];
#pragma unroll
    for (int k = 0; k < 4; k++) {
        rA[k] = Dp[(2 * k) * TLEN];
        rB[k] = Dp[(2 * k + 1) * TLEN];
        rH[k] = DpH[(2 * k) * TLEN];
    }

    float2 qY = make_float2(0.f, 0.f), qZ = make_float2(0.f, 0.f);

    auto fstep = [&](int p, int k) {
        const int d = 2 * p;
        // Deferred weight stores of previous phase (post-barrier).
        if (p >= 1) {
            Wp[(size_t)(d - 2) * TLEN] = qY;
            Wp[(size_t)(d - 1) * TLEN] = qZ;
        }

        float DY = rA[k], DZ = rB[k], DXv = rH[k];
        rA[k] = Dp[(d + 8) * TLEN];
        rB[k] = Dp[(d + 9) * TLEN];
        rH[k] = DpH[(d + 8) * TLEN];

        const float2* sPp = sP[(p + 1) & 1];
        float2 P0 = sPp[i];       // (R[d-2][i-2], R[d-1][i-2])
        float2 P1 = sPp[i + 1];   // (R[d-2][i-1], R[d-1][i-1])
        float2 P2 = sPp[i + 2];   // (R[d-2][i],   R[d-1][i])

        // X = R[d][i-1] (halo; no weights needed)
        bool vX = (i >= 1) && (i <= d + 1) && (d - i < 255);
        float mx = fminf(P0.x, fminf(P0.y, P1.y));
        float sx = ex2f_((mx - P0.x) * KE2) + ex2f_((mx - P0.y) * KE2)
                 + ex2f_((mx - P1.y) * KE2);
        float x = mx - KL * lg2f_(sx) + DXv;
        if (d == 0) x = DXv;
        if (!vX) x = BIGV;

        // Y = R[d][i]  (preds: diag=P1.x, up=P1.y, left=P2.y)
        bool vY = (i <= d) && (d - i < 256);
        float my = fminf(P1.x, fminf(P1.y, P2.y));
        float e0 = ex2f_((my - P1.x) * KE2);
        float e1 = ex2f_((my - P1.y) * KE2);
        float e2 = ex2f_((my - P2.y) * KE2);
        float sy = e0 + e1 + e2;
        float y  = my - KL * lg2f_(sy) + DY;
        float ry = rcpf_(sy);
        float2 wY = make_float2(e0 * ry, e1 * ry);
        if (d == 0 && i == 0) y = DY;
        if (!vY) y = BIGV;

        // Z = R[d+1][i]  (preds: diag=P1.y, up=x, left=y)
        bool vZ = (i <= d + 1) && (d - i < 255);
        float mz = fminf(P1.y, fminf(x, y));
        float f0 = ex2f_((mz - P1.y) * KE2);
        float f1 = ex2f_((mz - x) * KE2);
        float f2 = ex2f_((mz - y) * KE2);
        float sz = f0 + f1 + f2;
        float z  = mz - KL * lg2f_(sz) + DZ;
        float rz = rcpf_(sz);
        float2 wZ = make_float2(f0 * rz, f1 * rz);
        if (!vZ) z = BIGV;

        sP[p & 1][i + 2] = make_float2(y, z);
        qY = wY; qZ = wZ;
        __syncthreads();
    };

#pragma unroll 1
    for (int g = 0; g < 63; g++) {
#pragma unroll
        for (int k = 0; k < 4; k++) fstep(g * 4 + k, k);
    }
    fstep(252, 0); fstep(253, 1); fstep(254, 2);

    // Flush phase 254's deferred weight stores.
    Wp[(size_t)508 * TLEN] = qY;
    Wp[(size_t)509 * TLEN] = qZ;

    // Epilogue: diag 510 (reads phase 254's buffer = sP[0]).
    {
        const float2* sPp = sP[0];
        float m = fminf(sPp[i + 1].x, fminf(sPp[i + 1].y, sPp[i + 2].y));
        float e0 = ex2f_((m - sPp[i + 1].x) * KE2);
        float e1 = ex2f_((m - sPp[i + 1].y) * KE2);
        float e2 = ex2f_((m - sPp[i + 2].y) * KE2);
        float s = e0 + e1 + e2;
        float y = m - KL * lg2f_(s) + rA[3];
        float rs = rcpf_(s);
        Wp[(size_t)510 * TLEN] = make_float2(e0 * rs, e1 * rs);
        if (i == 255) g_shape[b] = y;   // R[255,255]
    }
}

// ---------------------------------------------------------------------------
// Kernel 3: gradient, reverse. LINEAR recurrence on products:
// cell c stores (E_c*w_dg, E_c*w_up, E_c*w_lf); then
// E[d][i] = lf(d+1,i) + up(d+1,i+1) + dg(d+2,i+1).  No exp, no MUFU.
// Phase p: Y = E[d][i] (d=510-2p), Z = E[d-1][i], halo X = E[d][i+1].
// 8-phase register rings on the three g_W streams.
// ---------------------------------------------------------------------------
__global__ __launch_bounds__(256) void bwd_kernel()
{
    __shared__ float4 sY4[2][258];   // products of diag d   (slots 256,257 = 0)
    __shared__ float4 sZ4[2][258];   // products of diag d-1
    __shared__ float red[16];

    const int b = blockIdx.x;
    const int i = threadIdx.x;

    for (int q = i; q < 2 * 258 * 4 * 2; q += 256) ((float*)sY4)[q] = 0.0f;
    __syncthreads();

    const float2* Wb  = g_W + ((size_t)b * NDIAGT + PAD) * TLEN;
    const float2* W0p = Wb + i;        // stream at col i
    const float2* WXp = Wb + i + 1;    // halo col i+1 (overflow lands in-array, finite)

    float2 rW0[8], rW1[8], rWX[8];
#pragma unroll
    for (int k = 0; k < 8; k++) {
        rW0[k] = W0p[(size_t)(510 - 2 * k) * TLEN];
        rW1[k] = W0p[(size_t)(509 - 2 * k) * TLEN];
        rWX[k] = WXp[(size_t)(510 - 2 * k) * TLEN];
    }

    float accS = 0.0f, accW = 0.0f;

    auto bstep = [&](int p, int k) {
        const int d = 510 - 2 * p;
        float2 wYv = rW0[k], wZv = rW1[k], wXv = rWX[k];
        rW0[k] = W0p[(size_t)(d - 16) * TLEN];
        rW1[k] = W0p[(size_t)(d - 17) * TLEN];
        rWX[k] = WXp[(size_t)(d - 16) * TLEN];

        const float4* pY = sY4[(p + 1) & 1];   // diag d+2 products
        const float4* pZ = sZ4[(p + 1) & 1];   // diag d+1 products

        float4 Z1 = pZ[i + 1];
        // Y = E[d][i]
        float Y = pZ[i].z + Z1.y + pY[i + 1].x;
        if (d == 510) Y = (i == 255) ? 1.0f : 0.0f;
        // X = E[d][i+1] (halo)
        float X = Z1.z + pZ[i + 2].y + pY[i + 2].x;
        if (d == 510) X = (i + 1 == 255) ? 1.0f : 0.0f;

        float wlfY = 1.0f - wYv.x - wYv.y;
        // Z = E[d-1][i] = dg(d+1,i+1) + X*w_up(d,i+1) + Y*w_lf(d,i)
        float Z = Z1.x + X * wXv.y + Y * wlfY;

        bool vY = (i <= d) && (d - i < 256);
        bool vZ = (i <= d - 1) && (d - 1 - i < 256);
        Y = vY ? Y : 0.0f;
        Z = vZ ? Z : 0.0f;

        accS += Y + Z;
        float dwy = (float)(2 * i - d);
        float dwz = (float)(2 * i - d + 1);
        accW = fmaf(Y, dwy * dwy, accW);
        accW = fmaf(Z, dwz * dwz, accW);

        float wlfZ = 1.0f - wZv.x - wZv.y;
        sY4[p & 1][i] = make_float4(Y * wYv.x, Y * wYv.y, Y * wlfY, 0.0f);
        sZ4[p & 1][i] = make_float4(Z * wZv.x, Z * wZv.y, Z * wlfZ, 0.0f);
        __syncthreads();
    };

#pragma unroll 1
    for (int g = 0; g < 31; g++) {
#pragma unroll
        for (int k = 0; k < 8; k++) bstep(g * 8 + k, k);
    }
#pragma unroll
    for (int k = 0; k < 7; k++) bstep(248 + k, k);   // p = 248..254 (d = 14..2)

    // Epilogue: E[0,0] (omega weight 0). Phase 254 buffers = index 0.
    if (i == 0) {
        float E00 = sZ4[0][0].z + sZ4[0][1].y + sY4[0][1].x;
        accS += E00;
    }

    accW *= (1.0f / (255.0f * 255.0f));

#pragma unroll
    for (int off = 16; off; off >>= 1) {
        accS += __shfl_down_sync(0xFFFFFFFFu, accS, off);
        accW += __shfl_down_sync(0xFFFFFFFFu, accW, off);
    }
    const int w = i >> 5, l = i & 31;
    if (l == 0) { red[w] = accS; red[w + 8] = accW; }
    __syncthreads();
    if (i == 0) {
        float s = 0.0f, wv = 0.0f;
#pragma unroll
        for (int q = 0; q < 8; q++) { s += red[q]; wv += red[q + 8]; }
        g_den[b] = s;
        g_num[b] = wv;
    }
}

// ---------------------------------------------------------------------------
// Kernel 4: final scalar.
// ---------------------------------------------------------------------------
__global__ void final_kernel(float* __restrict__ out)
{
    __shared__ float red[4];
    const int t = threadIdx.x;   // 128 threads, one per batch

    float shape = g_shape[t] * (1.0f / 256.0f);
    float den   = g_den[t]   * (1.0f / 256.0f);
    float num   = g_num[t]   * (1.0f / 256.0f);
    float temporal = num / fmaxf(den, 1e-8f);
    float val = 0.5f * shape + 0.5f * temporal;

#pragma unroll
    for (int off = 16; off; off >>= 1)
        val += __shfl_down_sync(0xFFFFFFFFu, val, off);
    if ((t & 31) == 0) red[t >> 5] = val;
    __syncthreads();
    if (t == 0)
        out[0] = (red[0] + red[1] + red[2] + red[3]) * (1.0f / 128.0f);
}

// ---------------------------------------------------------------------------
extern "C" void kernel_launch(void* const* d_in, const int* in_sizes, int n_in,
                              void* d_out, int out_size)
{
    const float* preds   = (const float*)d_in[0];
    const float* targets = (const float*)d_in[1];

    dist_kernel<<<dim3(4, 4, BATCH), 256>>>(preds, targets);
    fwd_kernel<<<BATCH, 256>>>();
    fwd_kernel<<<BATCH, 256>>>();   // DIAGNOSTIC duplicate (idempotent):
                                    // dur_us - 255.5 == fwd_kernel duration
    bwd_kernel<<<BATCH, 256>>>();
    final_kernel<<<1, 128>>>((float*)d_out);
}

// round 14
// speedup vs baseline: 1.7340x; 1.7340x over previous
#include <cuda_runtime.h>
#include <cuda_fp16.h>

// ---------------------------------------------------------------------------
// DILATE loss. B=128, T=256, D=64, gamma=0.01, alpha=0.5, eps=1e-8, BIG=1e10.
//
// Scratch compressed to fp16 and PAIR-PACKED in diagonal-major layout:
//   g_Dp[b][p][i]  = uint32  = (half D[2p][i], half D[2p+1][i])
//   g_WP[b][q][i]  = uint2   = (half2(wY of diag 2q), half2(wZ of diag 2q-1))
// fwd consumes D pairs (1 LDG.32 + same-line halo); bwd consumes W pairs
// (1 LDG.64 + same-line halo). Identity retained: forward softmin weights ==
// backward gradient edge weights; bwd is a linear recurrence on E*w products.
// ---------------------------------------------------------------------------

#define BATCH 128
#define TLEN  256
#define PADP  8                 // D-pair padding (fwd ring overshoot)
#define NDP   (256 + 2 * PADP)
#define PADW  8                 // W-pair padding (bwd ring overshoot)
#define NWP   (256 + 2 * PADW)
#define BIGV  1e10f
#define KE2   144.26950408889634f   // (1/gamma)*log2(e)
#define KL    0.006931471805599453f // gamma*ln(2)

__device__ unsigned int g_Dp[(size_t)BATCH * NDP * TLEN];
__device__ uint2        g_WP[(size_t)BATCH * NWP * TLEN];
__device__ float        g_shape[BATCH];
__device__ float        g_num[BATCH];
__device__ float        g_den[BATCH];

__device__ __forceinline__ float ex2f_(float x) {
    float y; asm("ex2.approx.ftz.f32 %0, %1;" : "=f"(y) : "f"(x)); return y;
}
__device__ __forceinline__ float lg2f_(float x) {
    float y; asm("lg2.approx.ftz.f32 %0, %1;" : "=f"(y) : "f"(x)); return y;
}
__device__ __forceinline__ float rcpf_(float x) {
    float y; asm("rcp.approx.ftz.f32 %0, %1;" : "=f"(y) : "f"(x)); return y;
}
__device__ __forceinline__ float2 up2(unsigned int u) {
    return __half22float2(*reinterpret_cast<__half2*>(&u));
}
__device__ __forceinline__ unsigned int pk2(float a, float b) {
    __half2 h = __floats2half2_rn(a, b);
    return *reinterpret_cast<unsigned int*>(&h);
}

// ---------------------------------------------------------------------------
// Kernel 1: pairwise squared distances -> fp16 pair-packed diagonal layout.
// ---------------------------------------------------------------------------
__global__ __launch_bounds__(256) void dist_kernel(
    const float* __restrict__ preds, const float* __restrict__ targets)
{
    __shared__ float pool[2 * 64 * 68 + 128];
    float*  ps  = pool;                   // [64][68]
    float*  ts  = pool + 64 * 68;
    float*  pn  = pool + 2 * 64 * 68;     // [64]
    float*  tn  = pn + 64;
    float4* ps4 = (float4*)ps;            // pitch 17
    float4* ts4 = (float4*)ts;

    const int b  = blockIdx.z;
    const int i0 = blockIdx.y * 64;
    const int j0 = blockIdx.x * 64;
    const int tid = threadIdx.x;

    const float4* pb4 = (const float4*)(preds   + (size_t)b * TLEN * 64 + (size_t)i0 * 64);
    const float4* tb4 = (const float4*)(targets + (size_t)b * TLEN * 64 + (size_t)j0 * 64);

#pragma unroll
    for (int q = 0; q < 4; q++) {
        int idx = q * 256 + tid;
        int r = idx >> 4, c4 = idx & 15;
        ps4[r * 17 + c4] = pb4[idx];
        ts4[r * 17 + c4] = tb4[idx];
    }
    __syncthreads();

    if (tid < 128) {
        const float* src = (tid < 64) ? ps : ts;
        float* dst = (tid < 64) ? pn : tn;
        int r = tid & 63;
        float s = 0.0f;
#pragma unroll
        for (int k = 0; k < 64; k++) { float v = src[r * 68 + k]; s = fmaf(v, v, s); }
        dst[r] = s;
    }
    __syncthreads();

    const int tx = tid & 15, ty = tid >> 4;
    const int ib = ty * 4, jb = tx * 4;

    float acc[4][4];
#pragma unroll
    for (int r = 0; r < 4; r++)
#pragma unroll
        for (int c = 0; c < 4; c++) acc[r][c] = 0.0f;

#pragma unroll 4
    for (int kq = 0; kq < 16; kq++) {
        float4 pv[4], tv[4];
#pragma unroll
        for (int r = 0; r < 4; r++) pv[r] = ps4[(ib + r) * 17 + kq];
#pragma unroll
        for (int c = 0; c < 4; c++) tv[c] = ts4[(jb + c) * 17 + kq];
#pragma unroll
        for (int r = 0; r < 4; r++)
#pragma unroll
            for (int c = 0; c < 4; c++) {
                acc[r][c] = fmaf(pv[r].x, tv[c].x, acc[r][c]);
                acc[r][c] = fmaf(pv[r].y, tv[c].y, acc[r][c]);
                acc[r][c] = fmaf(pv[r].z, tv[c].z, acc[r][c]);
                acc[r][c] = fmaf(pv[r].w, tv[c].w, acc[r][c]);
            }
    }

    float pnr[4], tnr[4];
#pragma unroll
    for (int r = 0; r < 4; r++) pnr[r] = pn[ib + r];
#pragma unroll
    for (int c = 0; c < 4; c++) tnr[c] = tn[jb + c];

    __syncthreads();

    // Stage tile diagonally: buf[tdd][ii], tdd = local i+j (0..126), pitch 65.
    float* buf = pool;
#pragma unroll
    for (int r = 0; r < 4; r++)
#pragma unroll
        for (int c = 0; c < 4; c++) {
            int ii = ib + r, jj = jb + c;
            float dv = pnr[r] + tnr[c] - 2.0f * acc[r][c];
            buf[(ii + jj) * 65 + ii] = fmaxf(dv, 0.0f);
        }
    __syncthreads();

    // fp16 scatter: cell (g = i0+j0+tdd, col = i0+ii) -> pair g>>1, half g&1.
    unsigned short* dbase = (unsigned short*)g_Dp;
    for (int base = 0; base < 128; base += 4) {
        int tdd = base + (tid >> 6);
        int ii  = tid & 63;
        if (tdd < 127) {
            int jj = tdd - ii;
            if (jj >= 0 && jj < 64) {
                int g = i0 + j0 + tdd;
                size_t off = (((size_t)b * NDP + PADP + (g >> 1)) * TLEN
                              + (i0 + ii)) * 2 + (g & 1);
                __half h = __float2half_rn(buf[tdd * 65 + ii]);
                dbase[off] = *reinterpret_cast<unsigned short*>(&h);
            }
        }
    }
}

// ---------------------------------------------------------------------------
// Kernel 2: soft-DTW forward. Phase p: diags d=2p (Y), d+1 (Z), halo X =
// R[d][i-1]. D pairs: 1 LDG.32 + same-line halo. W pairs (wY_2q, wZ_{2q-1})
// stored deferred. Ping-pong float2 smem sP[p&1][i+2] = (R_d[i], R_{d+1}[i]).
// ---------------------------------------------------------------------------
__global__ __launch_bounds__(256) void fwd_kernel()
{
    __shared__ float2 sP[2][260];   // [0..1] = BIG pad (never overwritten)
    const int b = blockIdx.x;
    const int i = threadIdx.x;

    for (int q = i; q < 2 * 260 * 2; q += 256) ((float*)sP)[q] = BIGV;
    __syncthreads();

    const unsigned int* DpP = g_Dp + ((size_t)b * NDP + PADP) * TLEN + i;
    const unsigned int* DpH = DpP - 1;      // halo col i-1 (pad rows keep i=0 safe)
    uint2*              WpP = g_WP + ((size_t)b * NWP + PADW) * TLEN + i;

    unsigned int rP[4], rHh[4];
#pragma unroll
    for (int k = 0; k < 4; k++) {
        rP[k]  = DpP[k * TLEN];
        rHh[k] = DpH[k * TLEN];
    }

    float2 qY = make_float2(0.f, 0.f);   // wY of phase p-1
    float2 qZ = make_float2(0.f, 0.f);   // wZ of phase p-1
    float2 qZ2 = make_float2(0.f, 0.f);  // wZ of phase p-2

    auto fstep = [&](int p, int k) {
        const int d = 2 * p;
        // Deferred pair store: pair p-1 = (wY_{p-1}, wZ_{p-2}).
        if (p >= 1)
            WpP[(size_t)(p - 1) * TLEN] = make_uint2(pk2(qY.x, qY.y), pk2(qZ2.x, qZ2.y));

        float2 Dyz = up2(rP[k]);
        float DY = Dyz.x, DZ = Dyz.y;
        float DXv = up2(rHh[k]).x;
        rP[k]  = DpP[(p + 4) * TLEN];
        rHh[k] = DpH[(p + 4) * TLEN];

        const float2* sPp = sP[(p + 1) & 1];
        float2 P0 = sPp[i];       // (R[d-2][i-2], R[d-1][i-2])
        float2 P1 = sPp[i + 1];   // (R[d-2][i-1], R[d-1][i-1])
        float2 P2 = sPp[i + 2];   // (R[d-2][i],   R[d-1][i])

        // X = R[d][i-1] (halo; no weights needed)
        bool vX = (i >= 1) && (i <= d + 1) && (d - i < 255);
        float mx = fminf(P0.x, fminf(P0.y, P1.y));
        float sx = ex2f_((mx - P0.x) * KE2) + ex2f_((mx - P0.y) * KE2)
                 + ex2f_((mx - P1.y) * KE2);
        float x = mx - KL * lg2f_(sx) + DXv;
        if (d == 0) x = DXv;
        if (!vX) x = BIGV;

        // Y = R[d][i]  (preds: diag=P1.x, up=P1.y, left=P2.y)
        bool vY = (i <= d) && (d - i < 256);
        float my = fminf(P1.x, fminf(P1.y, P2.y));
        float e0 = ex2f_((my - P1.x) * KE2);
        float e1 = ex2f_((my - P1.y) * KE2);
        float e2 = ex2f_((my - P2.y) * KE2);
        float sy = e0 + e1 + e2;
        float y  = my - KL * lg2f_(sy) + DY;
        float ry = rcpf_(sy);
        float2 wY = make_float2(e0 * ry, e1 * ry);
        if (d == 0 && i == 0) y = DY;
        if (!vY) y = BIGV;

        // Z = R[d+1][i]  (preds: diag=P1.y, up=x, left=y)
        bool vZ = (i <= d + 1) && (d - i < 255);
        float mz = fminf(P1.y, fminf(x, y));
        float f0 = ex2f_((mz - P1.y) * KE2);
        float f1 = ex2f_((mz - x) * KE2);
        float f2 = ex2f_((mz - y) * KE2);
        float sz = f0 + f1 + f2;
        float z  = mz - KL * lg2f_(sz) + DZ;
        float rz = rcpf_(sz);
        float2 wZ = make_float2(f0 * rz, f1 * rz);
        if (!vZ) z = BIGV;

        sP[p & 1][i + 2] = make_float2(y, z);
        qZ2 = qZ; qZ = wZ; qY = wY;
        __syncthreads();
    };

#pragma unroll 1
    for (int g = 0; g < 63; g++) {
#pragma unroll
        for (int k = 0; k < 4; k++) fstep(g * 4 + k, k);
    }
    fstep(252, 0); fstep(253, 1); fstep(254, 2);

    // Flush pair 254 = (wY_508, wZ_507).
    WpP[(size_t)254 * TLEN] = make_uint2(pk2(qY.x, qY.y), pk2(qZ2.x, qZ2.y));

    // Epilogue: diag 510 (reads phase 254's buffer = sP[0]); pair 255.
    {
        const float2* sPp = sP[0];
        float m = fminf(sPp[i + 1].x, fminf(sPp[i + 1].y, sPp[i + 2].y));
        float e0 = ex2f_((m - sPp[i + 1].x) * KE2);
        float e1 = ex2f_((m - sPp[i + 1].y) * KE2);
        float e2 = ex2f_((m - sPp[i + 2].y) * KE2);
        float s = e0 + e1 + e2;
        float D510 = up2(rP[3]).x;
        float y = m - KL * lg2f_(s) + D510;
        float rs = rcpf_(s);
        // pair 255 = (wY_510, wZ_509 = qZ)
        WpP[(size_t)255 * TLEN] = make_uint2(pk2(e0 * rs, e1 * rs), pk2(qZ.x, qZ.y));
        if (i == 255) g_shape[b] = y;   // R[255,255]
    }
}

// ---------------------------------------------------------------------------
// Kernel 3: gradient, reverse. Linear recurrence on E*w products (no MUFU).
// Phase p: pair q = 255-p -> Y = E[2q][i], Z = E[2q-1][i], halo X = E[2q][i+1].
// One W-pair stream (LDG.64) + same-line halo; 8-phase register rings.
// ---------------------------------------------------------------------------
__global__ __launch_bounds__(256) void bwd_kernel()
{
    __shared__ float4 sY4[2][258];   // products of diag d   (slots 256,257 = 0)
    __shared__ float4 sZ4[2][258];   // products of diag d-1
    __shared__ float red[16];

    const int b = blockIdx.x;
    const int i = threadIdx.x;

    for (int q = i; q < 2 * 258 * 4 * 2; q += 256) ((float*)sY4)[q] = 0.0f;
    __syncthreads();

    const uint2* WbP = g_WP + ((size_t)b * NWP + PADW) * TLEN + i;
    const uint2* WbX = WbP + 1;      // halo col i+1 (overflow lands in-array)

    uint2 rWP[8], rWX[8];
#pragma unroll
    for (int k = 0; k < 8; k++) {
        rWP[k] = WbP[(size_t)(255 - k) * TLEN];
        rWX[k] = WbX[(size_t)(255 - k) * TLEN];
    }

    float accS = 0.0f, accW = 0.0f;

    auto bstep = [&](int p, int k) {
        const int q = 255 - p;
        const int d = 2 * q;
        uint2 wp = rWP[k], wx = rWX[k];
        rWP[k] = WbP[(size_t)(q - 8) * TLEN];
        rWX[k] = WbX[(size_t)(q - 8) * TLEN];
        float2 wYv = up2(wp.x);   // weights of diag d   at col i
        float2 wZv = up2(wp.y);   // weights of diag d-1 at col i
        float2 wXv = up2(wx.x);   // weights of diag d   at col i+1

        const float4* pY = sY4[(p + 1) & 1];   // diag d+2 products
        const float4* pZ = sZ4[(p + 1) & 1];   // diag d+1 products

        float4 Z1 = pZ[i + 1];
        // Y = E[d][i]
        float Y = pZ[i].z + Z1.y + pY[i + 1].x;
        if (d == 510) Y = (i == 255) ? 1.0f : 0.0f;
        // X = E[d][i+1] (halo)
        float X = Z1.z + pZ[i + 2].y + pY[i + 2].x;
        if (d == 510) X = (i + 1 == 255) ? 1.0f : 0.0f;

        float wlfY = 1.0f - wYv.x - wYv.y;
        // Z = E[d-1][i] = dg(d+1,i+1) + X*w_up(d,i+1) + Y*w_lf(d,i)
        float Z = Z1.x + X * wXv.y + Y * wlfY;

        bool vY = (i <= d) && (d - i < 256);
        bool vZ = (i <= d - 1) && (d - 1 - i < 256);
        Y = vY ? Y : 0.0f;
        Z = vZ ? Z : 0.0f;

        accS += Y + Z;
        float dwy = (float)(2 * i - d);
        float dwz = (float)(2 * i - d + 1);
        accW = fmaf(Y, dwy * dwy, accW);
        accW = fmaf(Z, dwz * dwz, accW);

        float wlfZ = 1.0f - wZv.x - wZv.y;
        sY4[p & 1][i] = make_float4(Y * wYv.x, Y * wYv.y, Y * wlfY, 0.0f);
        sZ4[p & 1][i] = make_float4(Z * wZv.x, Z * wZv.y, Z * wlfZ, 0.0f);
        __syncthreads();
    };

#pragma unroll 1
    for (int g = 0; g < 31; g++) {
#pragma unroll
        for (int k = 0; k < 8; k++) bstep(g * 8 + k, k);
    }
#pragma unroll
    for (int k = 0; k < 7; k++) bstep(248 + k, k);   // p = 248..254 (d = 14..2)

    // Epilogue: E[0,0] (omega weight 0). Phase 254 buffers = index 0.
    if (i == 0) {
        float E00 = sZ4[0][0].z + sZ4[0][1].y + sY4[0][1].x;
        accS += E00;
    }

    accW *= (1.0f / (255.0f * 255.0f));

#pragma unroll
    for (int off = 16; off; off >>= 1) {
        accS += __shfl_down_sync(0xFFFFFFFFu, accS, off);
        accW += __shfl_down_sync(0xFFFFFFFFu, accW, off);
    }
    const int w = i >> 5, l = i & 31;
    if (l == 0) { red[w] = accS; red[w + 8] = accW; }
    __syncthreads();
    if (i == 0) {
        float s = 0.0f, wv = 0.0f;
#pragma unroll
        for (int q = 0; q < 8; q++) { s += red[q]; wv += red[q + 8]; }
        g_den[b] = s;
        g_num[b] = wv;
    }
}

// ---------------------------------------------------------------------------
// Kernel 4: final scalar.
// ---------------------------------------------------------------------------
__global__ void final_kernel(float* __restrict__ out)
{
    __shared__ float red[4];
    const int t = threadIdx.x;   // 128 threads, one per batch

    float shape = g_shape[t] * (1.0f / 256.0f);
    float den   = g_den[t]   * (1.0f / 256.0f);
    float num   = g_num[t]   * (1.0f / 256.0f);
    float temporal = num / fmaxf(den, 1e-8f);
    float val = 0.5f * shape + 0.5f * temporal;

#pragma unroll
    for (int off = 16; off; off >>= 1)
        val += __shfl_down_sync(0xFFFFFFFFu, val, off);
    if ((t & 31) == 0) red[t >> 5] = val;
    __syncthreads();
    if (t == 0)
        out[0] = (red[0] + red[1] + red[2] + red[3]) * (1.0f / 128.0f);
}

// ---------------------------------------------------------------------------
extern "C" void kernel_launch(void* const* d_in, const int* in_sizes, int n_in,
                              void* d_out, int out_size)
{
    const float* preds   = (const float*)d_in[0];
    const float* targets = (const float*)d_in[1];

    dist_kernel<<<dim3(4, 4, BATCH), 256>>>(preds, targets);
    fwd_kernel<<<BATCH, 256>>>();
    bwd_kernel<<<BATCH, 256>>>();
    final_kernel<<<1, 128>>>((float*)d_out);
}

// round 15
// speedup vs baseline: 2.2163x; 1.2781x over previous
#include <cuda_runtime.h>
#include <cuda_fp16.h>

// ---------------------------------------------------------------------------
// DILATE loss. B=128, T=256, D=64, gamma=0.01, alpha=0.5, eps=1e-8, BIG=1e10.
//
// fp16 pair-packed scratch (R14 layout):
//   g_Dp[b][p][i] = uint32 = (half D[2p][i], half D[2p+1][i])
//   g_WP[b][q][i] = uint2  = (half2 wY of diag 2q, half2 wZ of diag 2q-1)
// fwd: (v,s)-propagation removes lg2 from the recurrence (R = v - g*ln(s));
//      exact ALU renormalization keeps s in [1,2). One lg2 at the very end.
// dist: HFMA2 half2 mainloop, conflict-free 16-lane smem mapping.
// bwd: linear recurrence on E*w products (unchanged from R14).
// ---------------------------------------------------------------------------

#define BATCH 128
#define TLEN  256
#define PADP  8
#define NDP   (256 + 2 * PADP)
#define PADW  8
#define NWP   (256 + 2 * PADW)
#define BIGV  1e10f
#define KE2   144.26950408889634f   // (1/gamma)*log2(e)
#define KL    0.006931471805599453f // gamma*ln(2)

__device__ unsigned int g_Dp[(size_t)BATCH * NDP * TLEN];
__device__ uint2        g_WP[(size_t)BATCH * NWP * TLEN];
__device__ float        g_shape[BATCH];
__device__ float        g_num[BATCH];
__device__ float        g_den[BATCH];

__device__ __forceinline__ float ex2f_(float x) {
    float y; asm("ex2.approx.ftz.f32 %0, %1;" : "=f"(y) : "f"(x)); return y;
}
__device__ __forceinline__ float lg2f_(float x) {
    float y; asm("lg2.approx.ftz.f32 %0, %1;" : "=f"(y) : "f"(x)); return y;
}
__device__ __forceinline__ float rcpf_(float x) {
    float y; asm("rcp.approx.ftz.f32 %0, %1;" : "=f"(y) : "f"(x)); return y;
}
__device__ __forceinline__ float2 up2(unsigned int u) {
    return __half22float2(*reinterpret_cast<__half2*>(&u));
}
__device__ __forceinline__ unsigned int pk2(float a, float b) {
    __half2 h = __floats2half2_rn(a, b);
    return *reinterpret_cast<unsigned int*>(&h);
}

// ---------------------------------------------------------------------------
// Kernel 1: pairwise squared distances, HFMA2 mainloop, fp16 pair output.
// Thread tile: rows {ty+16r}, cols {tx+16c} (16-lane smem stride 33 == CF).
// ---------------------------------------------------------------------------
__global__ __launch_bounds__(256) void dist_kernel(
    const float* __restrict__ preds, const float* __restrict__ targets)
{
    __shared__ float pool[127 * 65 + 64];          // 33.3KB, phase-aliased
    unsigned* psh = reinterpret_cast<unsigned*>(pool);   // [64][33] half2 words
    unsigned* tsh = psh + 64 * 33;                       // [64][33]
    float*    pn  = reinterpret_cast<float*>(tsh + 64 * 33);  // [64]
    float*    tn  = pn + 64;

    const int b  = blockIdx.z;
    const int i0 = blockIdx.y * 64;
    const int j0 = blockIdx.x * 64;
    const int tid = threadIdx.x;

    const float4* pb4 = (const float4*)(preds   + (size_t)b * TLEN * 64 + (size_t)i0 * 64);
    const float4* tb4 = (const float4*)(targets + (size_t)b * TLEN * 64 + (size_t)j0 * 64);

#pragma unroll
    for (int q = 0; q < 4; q++) {
        int idx = q * 256 + tid;                 // 1024 float4 = 64 rows x 16
        int r = idx >> 4, c4 = idx & 15;
        float4 v = pb4[idx];
        psh[r * 33 + 2 * c4]     = pk2(v.x, v.y);
        psh[r * 33 + 2 * c4 + 1] = pk2(v.z, v.w);
        float4 w = tb4[idx];
        tsh[r * 33 + 2 * c4]     = pk2(w.x, w.y);
        tsh[r * 33 + 2 * c4 + 1] = pk2(w.z, w.w);
    }
    __syncthreads();

    if (tid < 128) {
        const unsigned* src = (tid < 64) ? psh : tsh;
        float* dst = (tid < 64) ? pn : tn;
        int r = tid & 63;
        float s = 0.0f;
#pragma unroll
        for (int k = 0; k < 32; k++) {
            float2 f = up2(src[r * 33 + k]);
            s = fmaf(f.x, f.x, fmaf(f.y, f.y, s));
        }
        dst[r] = s;
    }
    __syncthreads();

    const int tx = tid & 15, ty = tid >> 4;

    __half2 acc[4][4];
#pragma unroll
    for (int r = 0; r < 4; r++)
#pragma unroll
        for (int c = 0; c < 4; c++) acc[r][c] = __float2half2_rn(0.0f);

#pragma unroll 8
    for (int kq = 0; kq < 32; kq++) {
        __half2 pv[4], tv[4];
#pragma unroll
        for (int r = 0; r < 4; r++) {
            unsigned u = psh[(ty + 16 * r) * 33 + kq];
            pv[r] = *reinterpret_cast<__half2*>(&u);
        }
#pragma unroll
        for (int c = 0; c < 4; c++) {
            unsigned u = tsh[(tx + 16 * c) * 33 + kq];
            tv[c] = *reinterpret_cast<__half2*>(&u);
        }
#pragma unroll
        for (int r = 0; r < 4; r++)
#pragma unroll
            for (int c = 0; c < 4; c++)
                acc[r][c] = __hfma2(pv[r], tv[c], acc[r][c]);
    }

    float pnr[4], tnr[4];
#pragma unroll
    for (int r = 0; r < 4; r++) pnr[r] = pn[ty + 16 * r];
#pragma unroll
    for (int c = 0; c < 4; c++) tnr[c] = tn[tx + 16 * c];

    __syncthreads();   // done reading psh/tsh/pn/tn; pool becomes buf

    float* buf = pool;   // [127][65] diagonal staging
#pragma unroll
    for (int r = 0; r < 4; r++)
#pragma unroll
        for (int c = 0; c < 4; c++) {
            float2 f = __half22float2(acc[r][c]);
            float dot = f.x + f.y;
            int ii = ty + 16 * r, jj = tx + 16 * c;
            float dv = fmaxf(pnr[r] + tnr[c] - 2.0f * dot, 0.0f);
            buf[(ii + jj) * 65 + ii] = dv;
        }
    __syncthreads();

    // fp16 scatter: cell (g = i0+j0+tdd, col = i0+ii) -> pair g>>1, half g&1.
    unsigned short* dbase = (unsigned short*)g_Dp;
    for (int base = 0; base < 128; base += 4) {
        int tdd = base + (tid >> 6);
        int ii  = tid & 63;
        if (tdd < 127) {
            int jj = tdd - ii;
            if (jj >= 0 && jj < 64) {
                int g = i0 + j0 + tdd;
                size_t off = (((size_t)b * NDP + PADP + (g >> 1)) * TLEN
                              + (i0 + ii)) * 2 + (g & 1);
                __half h = __float2half_rn(buf[tdd * 65 + ii]);
                dbase[off] = *reinterpret_cast<unsigned short*>(&h);
            }
        }
    }
}

// ---------------------------------------------------------------------------
// Kernel 2: soft-DTW forward, (v,s)-propagation (no lg2 in the loop).
// Cell state: effective R = v - KL*lg2(s), s kept in [1,2) by exact halvings.
// Phase p: diags d=2p (Y), d+1 (Z), halo X = cell[d][i-1].
// smem sP[p&1][i+2] = (vY, sY, vZ, sZ). Weights pair-stored deferred.
// ---------------------------------------------------------------------------
__global__ __launch_bounds__(256) void fwd_kernel()
{
    __shared__ float4 sP[2][260];   // [0..1] pad = (BIG,1,BIG,1), never overwritten
    const int b = blockIdx.x;
    const int i = threadIdx.x;

    for (int q = i; q < 2 * 260; q += 256)
        ((float4*)sP)[q] = make_float4(BIGV, 1.0f, BIGV, 1.0f);
    __syncthreads();

    const unsigned int* DpP = g_Dp + ((size_t)b * NDP + PADP) * TLEN + i;
    const unsigned int* DpH = DpP - 1;      // halo col i-1 (pad rows keep i=0 safe)
    uint2*              WpP = g_WP + ((size_t)b * NWP + PADW) * TLEN + i;

    unsigned int rP[4], rHh[4];
#pragma unroll
    for (int k = 0; k < 4; k++) {
        rP[k]  = DpP[k * TLEN];
        rHh[k] = DpH[k * TLEN];
    }

    float2 qY  = make_float2(0.f, 0.f);   // wY of phase p-1
    float2 qZ  = make_float2(0.f, 0.f);   // wZ of phase p-1
    float2 qZ2 = make_float2(0.f, 0.f);   // wZ of phase p-2

    auto fstep = [&](int p, int k) {
        const int d = 2 * p;
        // Deferred pair store: pair p-1 = (wY_{phase p-1}, wZ_{phase p-2}).
        if (p >= 1)
            WpP[(size_t)(p - 1) * TLEN] = make_uint2(pk2(qY.x, qY.y), pk2(qZ2.x, qZ2.y));

        float2 Dyz = up2(rP[k]);
        float DY = Dyz.x, DZ = Dyz.y;
        float DXv = up2(rHh[k]).x;
        rP[k]  = DpP[(p + 4) * TLEN];
        rHh[k] = DpH[(p + 4) * TLEN];

        const float4* sPp = sP[(p + 1) & 1];
        float4 P0 = sPp[i];       // col i-2: (v_{d-2}, s_{d-2}, v_{d-1}, s_{d-1})
        float4 P1 = sPp[i + 1];   // col i-1
        float4 P2 = sPp[i + 2];   // col i

        // X = cell[d][i-1]: preds diag=(P0.x,P0.y), up=(P0.z,P0.w), left=(P1.z,P1.w)
        bool vXv = (i >= 1) && (i <= d + 1) && (d - i < 255);
        float mX = fminf(P0.x, fminf(P0.z, P1.z));
        float sx = P0.y * ex2f_((mX - P0.x) * KE2)
                 + P0.w * ex2f_((mX - P0.z) * KE2)
                 + P1.w * ex2f_((mX - P1.z) * KE2);
        float vx = mX + DXv;
        if (sx >= 2.0f) { sx *= 0.5f; vx += KL; }
        if (sx >= 2.0f) { sx *= 0.5f; vx += KL; }
        if (d == 0) { vx = DXv; sx = 1.0f; }
        if (!vXv)   { vx = BIGV; sx = 1.0f; }

        // Y = cell[d][i]: preds diag=(P1.x,P1.y), up=(P1.z,P1.w), left=(P2.z,P2.w)
        bool vYv = (i <= d) && (d - i < 256);
        float mY = fminf(P1.x, fminf(P1.z, P2.z));
        float e0 = P1.y * ex2f_((mY - P1.x) * KE2);
        float e1 = P1.w * ex2f_((mY - P1.z) * KE2);
        float e2 = P2.w * ex2f_((mY - P2.z) * KE2);
        float syr = e0 + e1 + e2;
        float ry = rcpf_(syr);
        float2 wY = make_float2(e0 * ry, e1 * ry);
        float vy = mY + DY, sy = syr;
        if (sy >= 2.0f) { sy *= 0.5f; vy += KL; }
        if (sy >= 2.0f) { sy *= 0.5f; vy += KL; }
        if (d == 0 && i == 0) { vy = DY; sy = 1.0f; }
        if (!vYv)             { vy = BIGV; sy = 1.0f; }

        // Z = cell[d+1][i]: preds diag=(P1.z,P1.w), up=(vx,sx), left=(vy,sy)
        bool vZv = (i <= d + 1) && (d - i < 255);
        float mZ = fminf(P1.z, fminf(vx, vy));
        float f0 = P1.w * ex2f_((mZ - P1.z) * KE2);
        float f1 = sx * ex2f_((mZ - vx) * KE2);
        float f2 = sy * ex2f_((mZ - vy) * KE2);
        float szr = f0 + f1 + f2;
        float rz = rcpf_(szr);
        float2 wZ = make_float2(f0 * rz, f1 * rz);
        float vz = mZ + DZ, sz = szr;
        if (sz >= 2.0f) { sz *= 0.5f; vz += KL; }
        if (sz >= 2.0f) { sz *= 0.5f; vz += KL; }
        if (!vZv) { vz = BIGV; sz = 1.0f; }

        sP[p & 1][i + 2] = make_float4(vy, sy, vz, sz);
        qZ2 = qZ; qZ = wZ; qY = wY;
        __syncthreads();
    };

#pragma unroll 1
    for (int g = 0; g < 63; g++) {
#pragma unroll
        for (int k = 0; k < 4; k++) fstep(g * 4 + k, k);
    }
    fstep(252, 0); fstep(253, 1); fstep(254, 2);

    // Flush pair 254 = (wY_508, wZ_507).
    WpP[(size_t)254 * TLEN] = make_uint2(pk2(qY.x, qY.y), pk2(qZ2.x, qZ2.y));

    // Epilogue: diag 510 (reads phase 254's buffer = sP[0]); pair 255.
    {
        float4 P1 = sP[0][i + 1];   // col i-1: (v508, s508, v509, s509)
        float4 P2 = sP[0][i + 2];   // col i
        float m = fminf(P1.x, fminf(P1.z, P2.z));
        float e0 = P1.y * ex2f_((m - P1.x) * KE2);
        float e1 = P1.w * ex2f_((m - P1.z) * KE2);
        float e2 = P2.w * ex2f_((m - P2.z) * KE2);
        float s = e0 + e1 + e2;
        float D510 = up2(rP[3]).x;
        float y = m - KL * lg2f_(s) + D510;   // the only lg2 in the kernel
        float rs = rcpf_(s);
        WpP[(size_t)255 * TLEN] = make_uint2(pk2(e0 * rs, e1 * rs), pk2(qZ.x, qZ.y));
        if (i == 255) g_shape[b] = y;   // R[255,255]
    }
}

// ---------------------------------------------------------------------------
// Kernel 3: gradient, reverse. Linear recurrence on E*w products (no MUFU).
// Phase p: pair q = 255-p -> Y = E[2q][i], Z = E[2q-1][i], halo X = E[2q][i+1].
// ---------------------------------------------------------------------------
__global__ __launch_bounds__(256) void bwd_kernel()
{
    __shared__ float4 sY4[2][258];   // products of diag d   (slots 256,257 = 0)
    __shared__ float4 sZ4[2][258];   // products of diag d-1
    __shared__ float red[16];

    const int b = blockIdx.x;
    const int i = threadIdx.x;

    for (int q = i; q < 2 * 258 * 4 * 2; q += 256) ((float*)sY4)[q] = 0.0f;
    __syncthreads();

    const uint2* WbP = g_WP + ((size_t)b * NWP + PADW) * TLEN + i;
    const uint2* WbX = WbP + 1;      // halo col i+1 (overflow lands in-array)

    uint2 rWP[8], rWX[8];
#pragma unroll
    for (int k = 0; k < 8; k++) {
        rWP[k] = WbP[(size_t)(255 - k) * TLEN];
        rWX[k] = WbX[(size_t)(255 - k) * TLEN];
    }

    float accS = 0.0f, accW = 0.0f;

    auto bstep = [&](int p, int k) {
        const int q = 255 - p;
        const int d = 2 * q;
        uint2 wp = rWP[k], wx = rWX[k];
        rWP[k] = WbP[(size_t)(q - 8) * TLEN];
        rWX[k] = WbX[(size_t)(q - 8) * TLEN];
        float2 wYv = up2(wp.x);   // weights of diag d   at col i
        float2 wZv = up2(wp.y);   // weights of diag d-1 at col i
        float2 wXv = up2(wx.x);   // weights of diag d   at col i+1

        const float4* pY = sY4[(p + 1) & 1];   // diag d+2 products
        const float4* pZ = sZ4[(p + 1) & 1];   // diag d+1 products

        float4 Z1 = pZ[i + 1];
        // Y = E[d][i]
        float Y = pZ[i].z + Z1.y + pY[i + 1].x;
        if (d == 510) Y = (i == 255) ? 1.0f : 0.0f;
        // X = E[d][i+1] (halo)
        float X = Z1.z + pZ[i + 2].y + pY[i + 2].x;
        if (d == 510) X = (i + 1 == 255) ? 1.0f : 0.0f;

        float wlfY = 1.0f - wYv.x - wYv.y;
        // Z = E[d-1][i] = dg(d+1,i+1) + X*w_up(d,i+1) + Y*w_lf(d,i)
        float Z = Z1.x + X * wXv.y + Y * wlfY;

        bool vY = (i <= d) && (d - i < 256);
        bool vZ = (i <= d - 1) && (d - 1 - i < 256);
        Y = vY ? Y : 0.0f;
        Z = vZ ? Z : 0.0f;

        accS += Y + Z;
        float dwy = (float)(2 * i - d);
        float dwz = (float)(2 * i - d + 1);
        accW = fmaf(Y, dwy * dwy, accW);
        accW = fmaf(Z, dwz * dwz, accW);

        float wlfZ = 1.0f - wZv.x - wZv.y;
        sY4[p & 1][i] = make_float4(Y * wYv.x, Y * wYv.y, Y * wlfY, 0.0f);
        sZ4[p & 1][i] = make_float4(Z * wZv.x, Z * wZv.y, Z * wlfZ, 0.0f);
        __syncthreads();
    };

#pragma unroll 1
    for (int g = 0; g < 31; g++) {
#pragma unroll
        for (int k = 0; k < 8; k++) bstep(g * 8 + k, k);
    }
#pragma unroll
    for (int k = 0; k < 7; k++) bstep(248 + k, k);   // p = 248..254 (d = 14..2)

    // Epilogue: E[0,0] (omega weight 0). Phase 254 buffers = index 0.
    if (i == 0) {
        float E00 = sZ4[0][0].z + sZ4[0][1].y + sY4[0][1].x;
        accS += E00;
    }

    accW *= (1.0f / (255.0f * 255.0f));

#pragma unroll
    for (int off = 16; off; off >>= 1) {
        accS += __shfl_down_sync(0xFFFFFFFFu, accS, off);
        accW += __shfl_down_sync(0xFFFFFFFFu, accW, off);
    }
    const int w = i >> 5, l = i & 31;
    if (l == 0) { red[w] = accS; red[w + 8] = accW; }
    __syncthreads();
    if (i == 0) {
        float s = 0.0f, wv = 0.0f;
#pragma unroll
        for (int q = 0; q < 8; q++) { s += red[q]; wv += red[q + 8]; }
        g_den[b] = s;
        g_num[b] = wv;
    }
}

// ---------------------------------------------------------------------------
// Kernel 4: final scalar.
// ---------------------------------------------------------------------------
__global__ void final_kernel(float* __restrict__ out)
{
    __shared__ float red[4];
    const int t = threadIdx.x;   // 128 threads, one per batch

    float shape = g_shape[t] * (1.0f / 256.0f);
    float den   = g_den[t]   * (1.0f / 256.0f);
    float num   = g_num[t]   * (1.0f / 256.0f);
    float temporal = num / fmaxf(den, 1e-8f);
    float val = 0.5f * shape + 0.5f * temporal;

#pragma unroll
    for (int off = 16; off; off >>= 1)
        val += __shfl_down_sync(0xFFFFFFFFu, val, off);
    if ((t & 31) == 0) red[t >> 5] = val;
    __syncthreads();
    if (t == 0)
        out[0] = (red[0] + red[1] + red[2] + red[3]) * (1.0f / 128.0f);
}

// ---------------------------------------------------------------------------
extern "C" void kernel_launch(void* const* d_in, const int* in_sizes, int n_in,
                              void* d_out, int out_size)
{
    const float* preds   = (const float*)d_in[0];
    const float* targets = (const float*)d_in[1];

    dist_kernel<<<dim3(4, 4, BATCH), 256>>>(preds, targets);
    fwd_kernel<<<BATCH, 256>>>();
    bwd_kernel<<<BATCH, 256>>>();
    final_kernel<<<1, 128>>>((float*)d_out);
}

// round 16
// speedup vs baseline: 2.3481x; 1.0595x over previous
#include <cuda_runtime.h>
#include <cuda_fp16.h>

// ---------------------------------------------------------------------------
// DILATE loss. B=128, T=256, D=64, gamma=0.01, alpha=0.5, eps=1e-8, BIG=1e10.
//
// fp16 pair-packed scratch:
//   g_Dp[b][p][i] = uint32 = (half D[2p][i], half D[2p+1][i])
//   g_WP[b][q][i] = uint2  = (half2 wY of diag 2q, half2 wZ of diag 2q-1)
// FUSED fwd+bwd kernel: per-CTA forward (v,s)-softmin sweep, barrier, then
// backward linear-recurrence sweep (E*w products). bwd stores only the
// consumed products: Y-diag needs just Y*w_dg (scalar), Z-diag needs all 3.
// ---------------------------------------------------------------------------

#define BATCH 128
#define TLEN  256
#define PADP  8
#define NDP   (256 + 2 * PADP)
#define PADW  8
#define NWP   (256 + 2 * PADW)
#define BIGV  1e10f
#define KE2   144.26950408889634f   // (1/gamma)*log2(e)
#define KL    0.006931471805599453f // gamma*ln(2)

__device__ unsigned int g_Dp[(size_t)BATCH * NDP * TLEN];
__device__ uint2        g_WP[(size_t)BATCH * NWP * TLEN];
__device__ float        g_shape[BATCH];
__device__ float        g_num[BATCH];
__device__ float        g_den[BATCH];

__device__ __forceinline__ float ex2f_(float x) {
    float y; asm("ex2.approx.ftz.f32 %0, %1;" : "=f"(y) : "f"(x)); return y;
}
__device__ __forceinline__ float lg2f_(float x) {
    float y; asm("lg2.approx.ftz.f32 %0, %1;" : "=f"(y) : "f"(x)); return y;
}
__device__ __forceinline__ float rcpf_(float x) {
    float y; asm("rcp.approx.ftz.f32 %0, %1;" : "=f"(y) : "f"(x)); return y;
}
__device__ __forceinline__ float2 up2(unsigned int u) {
    return __half22float2(*reinterpret_cast<__half2*>(&u));
}
__device__ __forceinline__ unsigned int pk2(float a, float b) {
    __half2 h = __floats2half2_rn(a, b);
    return *reinterpret_cast<unsigned int*>(&h);
}

// ---------------------------------------------------------------------------
// Kernel 1: pairwise squared distances, HFMA2 mainloop, fp16 pair output.
// ---------------------------------------------------------------------------
__global__ __launch_bounds__(256) void dist_kernel(
    const float* __restrict__ preds, const float* __restrict__ targets)
{
    __shared__ float pool[127 * 65 + 64];
    unsigned* psh = reinterpret_cast<unsigned*>(pool);        // [64][33]
    unsigned* tsh = psh + 64 * 33;                            // [64][33]
    float*    pn  = reinterpret_cast<float*>(tsh + 64 * 33);  // [64]
    float*    tn  = pn + 64;

    const int b  = blockIdx.z;
    const int i0 = blockIdx.y * 64;
    const int j0 = blockIdx.x * 64;
    const int tid = threadIdx.x;

    const float4* pb4 = (const float4*)(preds   + (size_t)b * TLEN * 64 + (size_t)i0 * 64);
    const float4* tb4 = (const float4*)(targets + (size_t)b * TLEN * 64 + (size_t)j0 * 64);

#pragma unroll
    for (int q = 0; q < 4; q++) {
        int idx = q * 256 + tid;
        int r = idx >> 4, c4 = idx & 15;
        float4 v = pb4[idx];
        psh[r * 33 + 2 * c4]     = pk2(v.x, v.y);
        psh[r * 33 + 2 * c4 + 1] = pk2(v.z, v.w);
        float4 w = tb4[idx];
        tsh[r * 33 + 2 * c4]     = pk2(w.x, w.y);
        tsh[r * 33 + 2 * c4 + 1] = pk2(w.z, w.w);
    }
    __syncthreads();

    if (tid < 128) {
        const unsigned* src = (tid < 64) ? psh : tsh;
        float* dst = (tid < 64) ? pn : tn;
        int r = tid & 63;
        float s = 0.0f;
#pragma unroll
        for (int k = 0; k < 32; k++) {
            float2 f = up2(src[r * 33 + k]);
            s = fmaf(f.x, f.x, fmaf(f.y, f.y, s));
        }
        dst[r] = s;
    }
    __syncthreads();

    const int tx = tid & 15, ty = tid >> 4;

    __half2 acc[4][4];
#pragma unroll
    for (int r = 0; r < 4; r++)
#pragma unroll
        for (int c = 0; c < 4; c++) acc[r][c] = __float2half2_rn(0.0f);

#pragma unroll 8
    for (int kq = 0; kq < 32; kq++) {
        __half2 pv[4], tv[4];
#pragma unroll
        for (int r = 0; r < 4; r++) {
            unsigned u = psh[(ty + 16 * r) * 33 + kq];
            pv[r] = *reinterpret_cast<__half2*>(&u);
        }
#pragma unroll
        for (int c = 0; c < 4; c++) {
            unsigned u = tsh[(tx + 16 * c) * 33 + kq];
            tv[c] = *reinterpret_cast<__half2*>(&u);
        }
#pragma unroll
        for (int r = 0; r < 4; r++)
#pragma unroll
            for (int c = 0; c < 4; c++)
                acc[r][c] = __hfma2(pv[r], tv[c], acc[r][c]);
    }

    float pnr[4], tnr[4];
#pragma unroll
    for (int r = 0; r < 4; r++) pnr[r] = pn[ty + 16 * r];
#pragma unroll
    for (int c = 0; c < 4; c++) tnr[c] = tn[tx + 16 * c];

    __syncthreads();

    float* buf = pool;   // [127][65] diagonal staging
#pragma unroll
    for (int r = 0; r < 4; r++)
#pragma unroll
        for (int c = 0; c < 4; c++) {
            float2 f = __half22float2(acc[r][c]);
            float dot = f.x + f.y;
            int ii = ty + 16 * r, jj = tx + 16 * c;
            float dv = fmaxf(pnr[r] + tnr[c] - 2.0f * dot, 0.0f);
            buf[(ii + jj) * 65 + ii] = dv;
        }
    __syncthreads();

    unsigned short* dbase = (unsigned short*)g_Dp;
    for (int base = 0; base < 128; base += 4) {
        int tdd = base + (tid >> 6);
        int ii  = tid & 63;
        if (tdd < 127) {
            int jj = tdd - ii;
            if (jj >= 0 && jj < 64) {
                int g = i0 + j0 + tdd;
                size_t off = (((size_t)b * NDP + PADP + (g >> 1)) * TLEN
                              + (i0 + ii)) * 2 + (g & 1);
                __half h = __float2half_rn(buf[tdd * 65 + ii]);
                dbase[off] = *reinterpret_cast<unsigned short*>(&h);
            }
        }
    }
}

// ---------------------------------------------------------------------------
// Kernel 2: FUSED soft-DTW forward + gradient for one batch per CTA.
// ---------------------------------------------------------------------------
#define SMEM_BYTES (2 * 258 * 16 + 2 * 258 * 4 + 64)   // bwd view (10384) > fwd (8320)

__global__ __launch_bounds__(256) void softdtw_kernel()
{
    __shared__ __align__(16) char smem_raw[SMEM_BYTES];
    const int b = blockIdx.x;
    const int i = threadIdx.x;

    // ======================= FORWARD (v,s) sweep ==========================
    {
        float4 (*sP)[260] = reinterpret_cast<float4(*)[260]>(smem_raw);

        for (int q = i; q < 2 * 260; q += 256)
            ((float4*)sP)[q] = make_float4(BIGV, 1.0f, BIGV, 1.0f);
        __syncthreads();

        const unsigned int* DpP = g_Dp + ((size_t)b * NDP + PADP) * TLEN + i;
        const unsigned int* DpH = DpP - 1;
        uint2*              WpP = g_WP + ((size_t)b * NWP + PADW) * TLEN + i;

        unsigned int rP[4], rHh[4];
#pragma unroll
        for (int k = 0; k < 4; k++) {
            rP[k]  = DpP[k * TLEN];
            rHh[k] = DpH[k * TLEN];
        }

        float2 qY  = make_float2(0.f, 0.f);
        float2 qZ  = make_float2(0.f, 0.f);
        float2 qZ2 = make_float2(0.f, 0.f);

        auto fstep = [&](int p, int k) {
            const int d = 2 * p;
            if (p >= 1)
                WpP[(size_t)(p - 1) * TLEN] =
                    make_uint2(pk2(qY.x, qY.y), pk2(qZ2.x, qZ2.y));

            float2 Dyz = up2(rP[k]);
            float DY = Dyz.x, DZ = Dyz.y;
            float DXv = up2(rHh[k]).x;
            rP[k]  = DpP[(p + 4) * TLEN];
            rHh[k] = DpH[(p + 4) * TLEN];

            const float4* sPp = sP[(p + 1) & 1];
            float4 P0 = sPp[i];
            float4 P1 = sPp[i + 1];
            float4 P2 = sPp[i + 2];

            // X = cell[d][i-1]
            bool vXv = (i >= 1) && (i <= d + 1) && (d - i < 255);
            float mX = fminf(P0.x, fminf(P0.z, P1.z));
            float sx = P0.y * ex2f_((mX - P0.x) * KE2)
                     + P0.w * ex2f_((mX - P0.z) * KE2)
                     + P1.w * ex2f_((mX - P1.z) * KE2);
            float vx = mX + DXv;
            if (sx >= 2.0f) { sx *= 0.5f; vx += KL; }
            if (sx >= 2.0f) { sx *= 0.5f; vx += KL; }
            if (d == 0) { vx = DXv; sx = 1.0f; }
            if (!vXv)   { vx = BIGV; sx = 1.0f; }

            // Y = cell[d][i]
            bool vYv = (i <= d) && (d - i < 256);
            float mY = fminf(P1.x, fminf(P1.z, P2.z));
            float e0 = P1.y * ex2f_((mY - P1.x) * KE2);
            float e1 = P1.w * ex2f_((mY - P1.z) * KE2);
            float e2 = P2.w * ex2f_((mY - P2.z) * KE2);
            float syr = e0 + e1 + e2;
            float ry = rcpf_(syr);
            float2 wY = make_float2(e0 * ry, e1 * ry);
            float vy = mY + DY, sy = syr;
            if (sy >= 2.0f) { sy *= 0.5f; vy += KL; }
            if (sy >= 2.0f) { sy *= 0.5f; vy += KL; }
            if (d == 0 && i == 0) { vy = DY; sy = 1.0f; }
            if (!vYv)             { vy = BIGV; sy = 1.0f; }

            // Z = cell[d+1][i]
            bool vZv = (i <= d + 1) && (d - i < 255);
            float mZ = fminf(P1.z, fminf(vx, vy));
            float f0 = P1.w * ex2f_((mZ - P1.z) * KE2);
            float f1 = sx * ex2f_((mZ - vx) * KE2);
            float f2 = sy * ex2f_((mZ - vy) * KE2);
            float szr = f0 + f1 + f2;
            float rz = rcpf_(szr);
            float2 wZ = make_float2(f0 * rz, f1 * rz);
            float vz = mZ + DZ, sz = szr;
            if (sz >= 2.0f) { sz *= 0.5f; vz += KL; }
            if (sz >= 2.0f) { sz *= 0.5f; vz += KL; }
            if (!vZv) { vz = BIGV; sz = 1.0f; }

            sP[p & 1][i + 2] = make_float4(vy, sy, vz, sz);
            qZ2 = qZ; qZ = wZ; qY = wY;
            __syncthreads();
        };

#pragma unroll 1
        for (int g = 0; g < 63; g++) {
#pragma unroll
            for (int k = 0; k < 4; k++) fstep(g * 4 + k, k);
        }
        fstep(252, 0); fstep(253, 1); fstep(254, 2);

        WpP[(size_t)254 * TLEN] = make_uint2(pk2(qY.x, qY.y), pk2(qZ2.x, qZ2.y));

        // Epilogue: diag 510; pair 255.
        {
            float4 P1 = sP[0][i + 1];
            float4 P2 = sP[0][i + 2];
            float m = fminf(P1.x, fminf(P1.z, P2.z));
            float e0 = P1.y * ex2f_((m - P1.x) * KE2);
            float e1 = P1.w * ex2f_((m - P1.z) * KE2);
            float e2 = P2.w * ex2f_((m - P2.z) * KE2);
            float s = e0 + e1 + e2;
            float D510 = up2(rP[3]).x;
            float y = m - KL * lg2f_(s) + D510;
            float rs = rcpf_(s);
            WpP[(size_t)255 * TLEN] =
                make_uint2(pk2(e0 * rs, e1 * rs), pk2(qZ.x, qZ.y));
            if (i == 255) g_shape[b] = y;   // R[255,255]
        }
    }

    __syncthreads();

    // ======================= BACKWARD linear sweep ========================
    {
        float4* sZ4 = reinterpret_cast<float4*>(smem_raw);            // [2][258]
        float*  sYd = reinterpret_cast<float*>(smem_raw + 2 * 258 * 16); // [2][258]
        float*  red = reinterpret_cast<float*>(smem_raw + 2 * 258 * 16 + 2 * 258 * 4);

        for (int q = i; q < 2 * 258 * 4 + 2 * 258 + 16; q += 256)
            ((float*)smem_raw)[q] = 0.0f;
        __syncthreads();

        const uint2* WbP = g_WP + ((size_t)b * NWP + PADW) * TLEN + i;
        const uint2* WbX = WbP + 1;

        uint2 rWP[8], rWX[8];
#pragma unroll
        for (int k = 0; k < 8; k++) {
            rWP[k] = WbP[(size_t)(255 - k) * TLEN];
            rWX[k] = WbX[(size_t)(255 - k) * TLEN];
        }

        float accS = 0.0f, accW = 0.0f;

        auto bstep = [&](int p, int k) {
            const int q = 255 - p;
            const int d = 2 * q;
            uint2 wp = rWP[k], wx = rWX[k];
            rWP[k] = WbP[(size_t)(q - 8) * TLEN];
            rWX[k] = WbX[(size_t)(q - 8) * TLEN];
            float2 wYv = up2(wp.x);
            float2 wZv = up2(wp.y);
            float2 wXv = up2(wx.x);

            const float4* pZ  = sZ4 + ((p + 1) & 1) * 258;   // diag d+1 products
            const float*  pYd = sYd + ((p + 1) & 1) * 258;   // diag d+2 dg-products

            float4 Z1 = pZ[i + 1];
            // Y = E[d][i]
            float Y = pZ[i].z + Z1.y + pYd[i + 1];
            if (d == 510) Y = (i == 255) ? 1.0f : 0.0f;
            // X = E[d][i+1] (halo)
            float X = Z1.z + pZ[i + 2].y + pYd[i + 2];
            if (d == 510) X = (i + 1 == 255) ? 1.0f : 0.0f;

            float wlfY = 1.0f - wYv.x - wYv.y;
            // Z = E[d-1][i]
            float Z = Z1.x + X * wXv.y + Y * wlfY;

            bool vY = (i <= d) && (d - i < 256);
            bool vZ = (i <= d - 1) && (d - 1 - i < 256);
            Y = vY ? Y : 0.0f;
            Z = vZ ? Z : 0.0f;

            accS += Y + Z;
            float dwy = (float)(2 * i - d);
            float dwz = (float)(2 * i - d + 1);
            accW = fmaf(Y, dwy * dwy, accW);
            accW = fmaf(Z, dwz * dwz, accW);

            float wlfZ = 1.0f - wZv.x - wZv.y;
            sYd[(p & 1) * 258 + i] = Y * wYv.x;
            sZ4[(p & 1) * 258 + i] = make_float4(Z * wZv.x, Z * wZv.y, Z * wlfZ, 0.0f);
            __syncthreads();
        };

#pragma unroll 1
        for (int g = 0; g < 31; g++) {
#pragma unroll
            for (int k = 0; k < 8; k++) bstep(g * 8 + k, k);
        }
#pragma unroll
        for (int k = 0; k < 7; k++) bstep(248 + k, k);   // p = 248..254

        // Epilogue: E[0,0] (omega weight 0). Phase 254 buffers = half 0.
        if (i == 0) {
            float E00 = sZ4[0].z + sZ4[1].y + sYd[1];
            accS += E00;
        }

        accW *= (1.0f / (255.0f * 255.0f));

#pragma unroll
        for (int off = 16; off; off >>= 1) {
            accS += __shfl_down_sync(0xFFFFFFFFu, accS, off);
            accW += __shfl_down_sync(0xFFFFFFFFu, accW, off);
        }
        const int w = i >> 5, l = i & 31;
        if (l == 0) { red[w] = accS; red[w + 8] = accW; }
        __syncthreads();
        if (i == 0) {
            float s = 0.0f, wv = 0.0f;
#pragma unroll
            for (int q = 0; q < 8; q++) { s += red[q]; wv += red[q + 8]; }
            g_den[b] = s;
            g_num[b] = wv;
        }
    }
}

// ---------------------------------------------------------------------------
// Kernel 3: final scalar.
// ---------------------------------------------------------------------------
__global__ void final_kernel(float* __restrict__ out)
{
    __shared__ float red[4];
    const int t = threadIdx.x;   // 128 threads, one per batch

    float shape = g_shape[t] * (1.0f / 256.0f);
    float den   = g_den[t]   * (1.0f / 256.0f);
    float num   = g_num[t]   * (1.0f / 256.0f);
    float temporal = num / fmaxf(den, 1e-8f);
    float val = 0.5f * shape + 0.5f * temporal;

#pragma unroll
    for (int off = 16; off; off >>= 1)
        val += __shfl_down_sync(0xFFFFFFFFu, val, off);
    if ((t & 31) == 0) red[t >> 5] = val;
    __syncthreads();
    if (t == 0)
        out[0] = (red[0] + red[1] + red[2] + red[3]) * (1.0f / 128.0f);
}

// ---------------------------------------------------------------------------
extern "C" void kernel_launch(void* const* d_in, const int* in_sizes, int n_in,
                              void* d_out, int out_size)
{
    const float* preds   = (const float*)d_in[0];
    const float* targets = (const float*)d_in[1];

    dist_kernel<<<dim3(4, 4, BATCH), 256>>>(preds, targets);
    softdtw_kernel<<<BATCH, 256>>>();
    final_kernel<<<1, 128>>>((float*)d_out);
}

// round 17
// speedup vs baseline: 2.5237x; 1.0748x over previous
#include <cuda_runtime.h>
#include <cuda_fp16.h>

// ---------------------------------------------------------------------------
// DILATE loss. B=128, T=256, D=64, gamma=0.01, alpha=0.5, eps=1e-8, BIG=1e10.
//
// dist: tensor-core GEMM (mma.sync.m16n8k16 f16->f32) for the Gram matrix,
//       fp16 pair-packed diagonal output.
// fwd:  (v,s)-softmin sweep emitting gradient edge weights (fp16 pairs).
// bwd:  linear recurrence on E*w products (fused with fwd, one CTA per batch).
// ---------------------------------------------------------------------------

#define BATCH 128
#define TLEN  256
#define PADP  8
#define NDP   (256 + 2 * PADP)
#define PADW  8
#define NWP   (256 + 2 * PADW)
#define BIGV  1e10f
#define KE2   144.26950408889634f   // (1/gamma)*log2(e)
#define KL    0.006931471805599453f // gamma*ln(2)

__device__ unsigned int g_Dp[(size_t)BATCH * NDP * TLEN];
__device__ uint2        g_WP[(size_t)BATCH * NWP * TLEN];
__device__ float        g_shape[BATCH];
__device__ float        g_num[BATCH];
__device__ float        g_den[BATCH];

__device__ __forceinline__ float ex2f_(float x) {
    float y; asm("ex2.approx.ftz.f32 %0, %1;" : "=f"(y) : "f"(x)); return y;
}
__device__ __forceinline__ float lg2f_(float x) {
    float y; asm("lg2.approx.ftz.f32 %0, %1;" : "=f"(y) : "f"(x)); return y;
}
__device__ __forceinline__ float rcpf_(float x) {
    float y; asm("rcp.approx.ftz.f32 %0, %1;" : "=f"(y) : "f"(x)); return y;
}
__device__ __forceinline__ float2 up2(unsigned int u) {
    return __half22float2(*reinterpret_cast<__half2*>(&u));
}
__device__ __forceinline__ unsigned int pk2(float a, float b) {
    __half2 h = __floats2half2_rn(a, b);
    return *reinterpret_cast<unsigned int*>(&h);
}

// ---------------------------------------------------------------------------
// Kernel 1: pairwise squared distances via tensor cores.
// smem tiles: [64][72] halves (pitch 144B). Per warp: 16x32 output tile.
// ---------------------------------------------------------------------------
__global__ __launch_bounds__(256) void dist_kernel(
    const float* __restrict__ preds, const float* __restrict__ targets)
{
    __shared__ float pool[127 * 65 + 64];     // 33.3KB, phase-aliased
    unsigned* psw = reinterpret_cast<unsigned*>(pool);        // [64][36] words
    unsigned* tsw = psw + 64 * 36;                            // [64][36] words
    float*    pn  = pool + 2 * 64 * 36;                       // [64]
    float*    tn  = pn + 64;

    const int b  = blockIdx.z;
    const int i0 = blockIdx.y * 64;
    const int j0 = blockIdx.x * 64;
    const int tid = threadIdx.x;

    const float4* pb4 = (const float4*)(preds   + (size_t)b * TLEN * 64 + (size_t)i0 * 64);
    const float4* tb4 = (const float4*)(targets + (size_t)b * TLEN * 64 + (size_t)j0 * 64);

#pragma unroll
    for (int q = 0; q < 4; q++) {
        int idx = q * 256 + tid;                 // 1024 float4 = 64 rows x 16
        int r = idx >> 4, c4 = idx & 15;
        float4 v = pb4[idx];
        psw[r * 36 + 2 * c4]     = pk2(v.x, v.y);
        psw[r * 36 + 2 * c4 + 1] = pk2(v.z, v.w);
        float4 w = tb4[idx];
        tsw[r * 36 + 2 * c4]     = pk2(w.x, w.y);
        tsw[r * 36 + 2 * c4 + 1] = pk2(w.z, w.w);
    }
    __syncthreads();

    if (tid < 128) {
        const unsigned* src = (tid < 64) ? psw : tsw;
        float* dst = (tid < 64) ? pn : tn;
        int r = tid & 63;
        float s = 0.0f;
#pragma unroll
        for (int k = 0; k < 32; k++) {
            float2 f = up2(src[r * 36 + k]);
            s = fmaf(f.x, f.x, fmaf(f.y, f.y, s));
        }
        dst[r] = s;
    }
    __syncthreads();

    // ---- tensor-core mainloop ----
    const int w = tid >> 5, l = tid & 31;
    const int wr = (w & 3) * 16;    // warp output rows (preds)
    const int wc = (w >> 2) * 32;   // warp output cols (targets)

    unsigned psh_base = (unsigned)__cvta_generic_to_shared(psw);
    unsigned tsh_base = (unsigned)__cvta_generic_to_shared(tsw);

    float c[4][4];
#pragma unroll
    for (int nt = 0; nt < 4; nt++)
#pragma unroll
        for (int r = 0; r < 4; r++) c[nt][r] = 0.0f;

#pragma unroll
    for (int ks = 0; ks < 4; ks++) {
        const int k0 = ks * 16;
        // A fragment: rows wr+(l&15), col half k0 + 8*(l>>4)   [halves]
        unsigned a0, a1, a2, a3;
        {
            unsigned addr = psh_base +
                ((wr + (l & 15)) * 72 + k0 + 8 * (l >> 4)) * 2;
            asm volatile(
                "ldmatrix.sync.aligned.m8n8.x4.shared.b16 {%0,%1,%2,%3}, [%4];"
                : "=r"(a0), "=r"(a1), "=r"(a2), "=r"(a3) : "r"(addr));
        }
#pragma unroll
        for (int nt = 0; nt < 4; nt++) {
            const int jj0 = wc + nt * 8;
            unsigned b0, b1;
            {
                unsigned addr = tsh_base +
                    ((jj0 + (l & 7)) * 72 + k0 + 8 * ((l >> 3) & 1)) * 2;
                asm volatile(
                    "ldmatrix.sync.aligned.m8n8.x2.shared.b16 {%0,%1}, [%2];"
                    : "=r"(b0), "=r"(b1) : "r"(addr));
            }
            asm volatile(
                "mma.sync.aligned.m16n8k16.row.col.f32.f16.f16.f32 "
                "{%0,%1,%2,%3}, {%4,%5,%6,%7}, {%8,%9}, {%0,%1,%2,%3};"
                : "+f"(c[nt][0]), "+f"(c[nt][1]), "+f"(c[nt][2]), "+f"(c[nt][3])
                : "r"(a0), "r"(a1), "r"(a2), "r"(a3), "r"(b0), "r"(b1));
        }
    }

    // Pull norms into registers before buf overwrites them.
    const int er0 = wr + (l >> 2);        // rows for c0/c1
    const int er1 = er0 + 8;              // rows for c2/c3
    float pn0 = pn[er0], pn1 = pn[er1];
    float tnr[8];
#pragma unroll
    for (int nt = 0; nt < 4; nt++) {
        tnr[2 * nt]     = tn[wc + nt * 8 + 2 * (l & 3)];
        tnr[2 * nt + 1] = tn[wc + nt * 8 + 2 * (l & 3) + 1];
    }
    __syncthreads();

    // Stage tile diagonally: buf[tdd][ii], tdd = local i+j, pitch 65.
    float* buf = pool;
#pragma unroll
    for (int nt = 0; nt < 4; nt++) {
        int jc0 = wc + nt * 8 + 2 * (l & 3);
#pragma unroll
        for (int r = 0; r < 4; r++) {
            int ii = (r < 2) ? er0 : er1;
            int jj = jc0 + (r & 1);
            float pnv = (r < 2) ? pn0 : pn1;
            float dv = fmaxf(pnv + tnr[2 * nt + (r & 1)] - 2.0f * c[nt][r], 0.0f);
            buf[(ii + jj) * 65 + ii] = dv;
        }
    }
    __syncthreads();

    unsigned short* dbase = (unsigned short*)g_Dp;
    for (int base = 0; base < 128; base += 4) {
        int tdd = base + (tid >> 6);
        int ii  = tid & 63;
        if (tdd < 127) {
            int jj = tdd - ii;
            if (jj >= 0 && jj < 64) {
                int g = i0 + j0 + tdd;
                size_t off = (((size_t)b * NDP + PADP + (g >> 1)) * TLEN
                              + (i0 + ii)) * 2 + (g & 1);
                __half h = __float2half_rn(buf[tdd * 65 + ii]);
                dbase[off] = *reinterpret_cast<unsigned short*>(&h);
            }
        }
    }
}

// ---------------------------------------------------------------------------
// Kernel 2: FUSED soft-DTW forward + gradient for one batch per CTA.
// ---------------------------------------------------------------------------
#define SMEM_BYTES (2 * 258 * 16 + 2 * 258 * 4 + 64)

__global__ __launch_bounds__(256) void softdtw_kernel()
{
    __shared__ __align__(16) char smem_raw[SMEM_BYTES];
    const int b = blockIdx.x;
    const int i = threadIdx.x;

    // ======================= FORWARD (v,s) sweep ==========================
    {
        float4 (*sP)[260] = reinterpret_cast<float4(*)[260]>(smem_raw);

        for (int q = i; q < 2 * 260; q += 256)
            ((float4*)sP)[q] = make_float4(BIGV, 1.0f, BIGV, 1.0f);
        __syncthreads();

        const unsigned int* DpP = g_Dp + ((size_t)b * NDP + PADP) * TLEN + i;
        const unsigned int* DpH = DpP - 1;
        uint2*              WpP = g_WP + ((size_t)b * NWP + PADW) * TLEN + i;

        unsigned int rP[4], rHh[4];
#pragma unroll
        for (int k = 0; k < 4; k++) {
            rP[k]  = DpP[k * TLEN];
            rHh[k] = DpH[k * TLEN];
        }

        float2 qY  = make_float2(0.f, 0.f);
        float2 qZ  = make_float2(0.f, 0.f);
        float2 qZ2 = make_float2(0.f, 0.f);

        auto fstep = [&](int p, int k) {
            const int d = 2 * p;
            if (p >= 1)
                WpP[(size_t)(p - 1) * TLEN] =
                    make_uint2(pk2(qY.x, qY.y), pk2(qZ2.x, qZ2.y));

            float2 Dyz = up2(rP[k]);
            float DY = Dyz.x, DZ = Dyz.y;
            float DXv = up2(rHh[k]).x;
            rP[k]  = DpP[(p + 4) * TLEN];
            rHh[k] = DpH[(p + 4) * TLEN];

            const float4* sPp = sP[(p + 1) & 1];
            float4 P0 = sPp[i];
            float4 P1 = sPp[i + 1];
            float4 P2 = sPp[i + 2];

            // X = cell[d][i-1]
            bool vXv = (i >= 1) && (i <= d + 1) && (d - i < 255);
            float mX = fminf(P0.x, fminf(P0.z, P1.z));
            float sx = P0.y * ex2f_((mX - P0.x) * KE2)
                     + P0.w * ex2f_((mX - P0.z) * KE2)
                     + P1.w * ex2f_((mX - P1.z) * KE2);
            float vx = mX + DXv;
            if (sx >= 2.0f) { sx *= 0.5f; vx += KL; }
            if (sx >= 2.0f) { sx *= 0.5f; vx += KL; }
            if (d == 0) { vx = DXv; sx = 1.0f; }
            if (!vXv)   { vx = BIGV; sx = 1.0f; }

            // Y = cell[d][i]
            bool vYv = (i <= d) && (d - i < 256);
            float mY = fminf(P1.x, fminf(P1.z, P2.z));
            float e0 = P1.y * ex2f_((mY - P1.x) * KE2);
            float e1 = P1.w * ex2f_((mY - P1.z) * KE2);
            float e2 = P2.w * ex2f_((mY - P2.z) * KE2);
            float syr = e0 + e1 + e2;
            float ry = rcpf_(syr);
            float2 wY = make_float2(e0 * ry, e1 * ry);
            float vy = mY + DY, sy = syr;
            if (sy >= 2.0f) { sy *= 0.5f; vy += KL; }
            if (sy >= 2.0f) { sy *= 0.5f; vy += KL; }
            if (d == 0 && i == 0) { vy = DY; sy = 1.0f; }
            if (!vYv)             { vy = BIGV; sy = 1.0f; }

            // Z = cell[d+1][i]
            bool vZv = (i <= d + 1) && (d - i < 255);
            float mZ = fminf(P1.z, fminf(vx, vy));
            float f0 = P1.w * ex2f_((mZ - P1.z) * KE2);
            float f1 = sx * ex2f_((mZ - vx) * KE2);
            float f2 = sy * ex2f_((mZ - vy) * KE2);
            float szr = f0 + f1 + f2;
            float rz = rcpf_(szr);
            float2 wZ = make_float2(f0 * rz, f1 * rz);
            float vz = mZ + DZ, sz = szr;
            if (sz >= 2.0f) { sz *= 0.5f; vz += KL; }
            if (sz >= 2.0f) { sz *= 0.5f; vz += KL; }
            if (!vZv) { vz = BIGV; sz = 1.0f; }

            sP[p & 1][i + 2] = make_float4(vy, sy, vz, sz);
            qZ2 = qZ; qZ = wZ; qY = wY;
            __syncthreads();
        };

#pragma unroll 1
        for (int g = 0; g < 63; g++) {
#pragma unroll
            for (int k = 0; k < 4; k++) fstep(g * 4 + k, k);
        }
        fstep(252, 0); fstep(253, 1); fstep(254, 2);

        WpP[(size_t)254 * TLEN] = make_uint2(pk2(qY.x, qY.y), pk2(qZ2.x, qZ2.y));

        // Epilogue: diag 510; pair 255.
        {
            float4 P1 = sP[0][i + 1];
            float4 P2 = sP[0][i + 2];
            float m = fminf(P1.x, fminf(P1.z, P2.z));
            float e0 = P1.y * ex2f_((m - P1.x) * KE2);
            float e1 = P1.w * ex2f_((m - P1.z) * KE2);
            float e2 = P2.w * ex2f_((m - P2.z) * KE2);
            float s = e0 + e1 + e2;
            float D510 = up2(rP[3]).x;
            float y = m - KL * lg2f_(s) + D510;
            float rs = rcpf_(s);
            WpP[(size_t)255 * TLEN] =
                make_uint2(pk2(e0 * rs, e1 * rs), pk2(qZ.x, qZ.y));
            if (i == 255) g_shape[b] = y;   // R[255,255]
        }
    }

    __syncthreads();

    // ======================= BACKWARD linear sweep ========================
    {
        float4* sZ4 = reinterpret_cast<float4*>(smem_raw);               // [2][258]
        float*  sYd = reinterpret_cast<float*>(smem_raw + 2 * 258 * 16); // [2][258]
        float*  red = reinterpret_cast<float*>(smem_raw + 2 * 258 * 16 + 2 * 258 * 4);

        for (int q = i; q < 2 * 258 * 4 + 2 * 258 + 16; q += 256)
            ((float*)smem_raw)[q] = 0.0f;
        __syncthreads();

        const uint2* WbP = g_WP + ((size_t)b * NWP + PADW) * TLEN + i;
        const uint2* WbX = WbP + 1;

        uint2 rWP[8], rWX[8];
#pragma unroll
        for (int k = 0; k < 8; k++) {
            rWP[k] = WbP[(size_t)(255 - k) * TLEN];
            rWX[k] = WbX[(size_t)(255 - k) * TLEN];
        }

        float accS = 0.0f, accW = 0.0f;

        auto bstep = [&](int p, int k) {
            const int q = 255 - p;
            const int d = 2 * q;
            uint2 wp = rWP[k], wx = rWX[k];
            rWP[k] = WbP[(size_t)(q - 8) * TLEN];
            rWX[k] = WbX[(size_t)(q - 8) * TLEN];
            float2 wYv = up2(wp.x);
            float2 wZv = up2(wp.y);
            float2 wXv = up2(wx.x);

            const float4* pZ  = sZ4 + ((p + 1) & 1) * 258;
            const float*  pYd = sYd + ((p + 1) & 1) * 258;

            float4 Z1 = pZ[i + 1];
            float Y = pZ[i].z + Z1.y + pYd[i + 1];
            if (d == 510) Y = (i == 255) ? 1.0f : 0.0f;
            float X = Z1.z + pZ[i + 2].y + pYd[i + 2];
            if (d == 510) X = (i + 1 == 255) ? 1.0f : 0.0f;

            float wlfY = 1.0f - wYv.x - wYv.y;
            float Z = Z1.x + X * wXv.y + Y * wlfY;

            bool vY = (i <= d) && (d - i < 256);
            bool vZ = (i <= d - 1) && (d - 1 - i < 256);
            Y = vY ? Y : 0.0f;
            Z = vZ ? Z : 0.0f;

            accS += Y + Z;
            float dwy = (float)(2 * i - d);
            float dwz = (float)(2 * i - d + 1);
            accW = fmaf(Y, dwy * dwy, accW);
            accW = fmaf(Z, dwz * dwz, accW);

            float wlfZ = 1.0f - wZv.x - wZv.y;
            sYd[(p & 1) * 258 + i] = Y * wYv.x;
            sZ4[(p & 1) * 258 + i] = make_float4(Z * wZv.x, Z * wZv.y, Z * wlfZ, 0.0f);
            __syncthreads();
        };

#pragma unroll 1
        for (int g = 0; g < 31; g++) {
#pragma unroll
            for (int k = 0; k < 8; k++) bstep(g * 8 + k, k);
        }
#pragma unroll
        for (int k = 0; k < 7; k++) bstep(248 + k, k);   // p = 248..254

        if (i == 0) {
            float E00 = sZ4[0].z + sZ4[1].y + sYd[1];
            accS += E00;
        }

        accW *= (1.0f / (255.0f * 255.0f));

#pragma unroll
        for (int off = 16; off; off >>= 1) {
            accS += __shfl_down_sync(0xFFFFFFFFu, accS, off);
            accW += __shfl_down_sync(0xFFFFFFFFu, accW, off);
        }
        const int w = i >> 5, l = i & 31;
        if (l == 0) { red[w] = accS; red[w + 8] = accW; }
        __syncthreads();
        if (i == 0) {
            float s = 0.0f, wv = 0.0f;
#pragma unroll
            for (int q = 0; q < 8; q++) { s += red[q]; wv += red[q + 8]; }
            g_den[b] = s;
            g_num[b] = wv;
        }
    }
}

// ---------------------------------------------------------------------------
// Kernel 3: final scalar.
// ---------------------------------------------------------------------------
__global__ void final_kernel(float* __restrict__ out)
{
    __shared__ float red[4];
    const int t = threadIdx.x;   // 128 threads, one per batch

    float shape = g_shape[t] * (1.0f / 256.0f);
    float den   = g_den[t]   * (1.0f / 256.0f);
    float num   = g_num[t]   * (1.0f / 256.0f);
    float temporal = num / fmaxf(den, 1e-8f);
    float val = 0.5f * shape + 0.5f * temporal;

#pragma unroll
    for (int off = 16; off; off >>= 1)
        val += __shfl_down_sync(0xFFFFFFFFu, val, off);
    if ((t & 31) == 0) red[t >> 5] = val;
    __syncthreads();
    if (t == 0)
        out[0] = (red[0] + red[1] + red[2] + red[3]) * (1.0f / 128.0f);
}

// ---------------------------------------------------------------------------
extern "C" void kernel_launch(void* const* d_in, const int* in_sizes, int n_in,
                              void* d_out, int out_size)
{
    const float* preds   = (const float*)d_in[0];
    const float* targets = (const float*)d_in[1];

    dist_kernel<<<dim3(4, 4, BATCH), 256>>>(preds, targets);
    softdtw_kernel<<<BATCH, 256>>>();
    final_kernel<<<1, 128>>>((float*)d_out);
}